// round 15
// baseline (speedup 1.0000x reference)
#include <cuda_runtime.h>
#include <math_constants.h>

#define BATCH 8
#define NPTS  4096
#define KNN   20
#define KSW   32
#define ROWS_PER_BLOCK 32     // 16 warps x 2 rows
#define THREADS 512
#define FULL 0xffffffffu

#define IDX_COUNT (BATCH * NPTS * KNN)

typedef unsigned long long ull;

// ---- f32x2 packed helpers (sm_103a; per-lane IEEE fp32 RN, bit-exact) ----
__device__ __forceinline__ ull pk2(float lo, float hi)
{ ull r; asm("mov.b64 %0, {%1, %2};" : "=l"(r) : "f"(lo), "f"(hi)); return r; }
__device__ __forceinline__ void upk2(ull p, float& lo, float& hi)
{ asm("mov.b64 {%0, %1}, %2;" : "=f"(lo), "=f"(hi) : "l"(p)); }
__device__ __forceinline__ ull fma2(ull a, ull b, ull c)
{ ull r; asm("fma.rn.f32x2 %0, %1, %2, %3;" : "=l"(r) : "l"(a), "l"(b), "l"(c)); return r; }
__device__ __forceinline__ ull mul2(ull a, ull b)
{ ull r; asm("mul.rn.f32x2 %0, %1, %2;" : "=l"(r) : "l"(a), "l"(b)); return r; }
__device__ __forceinline__ ull add2(ull a, ull b)
{ ull r; asm("add.rn.f32x2 %0, %1, %2;" : "=l"(r) : "l"(a), "l"(b)); return r; }

// SoA position map: within each 64-block, pos = B + 2*(j&31) + ((j>>5)&1).
// A single LDS.64 at B+2*lane yields {j=B+lane (lo), j=B+32+lane (hi)} packed.
__device__ __forceinline__ int posmap(int j)
{ return (j & ~63) + 2 * (j & 31) + ((j >> 5) & 1); }
__device__ __forceinline__ int invpos(int p)
{ return (p & ~63) + ((p >> 1) & 31) + ((p & 1) << 5); }

// Full bitonic sort of 32 (v, p) pairs across the warp, descending by
// (v desc, p asc on ties). Seed elements all have h=0 in one block, so pos
// order == original-j order; 2-field comparator required here.
__device__ __forceinline__ void bitonic32(float& v, int& j, const int lane)
{
#pragma unroll
    for (int k = 2; k <= 32; k <<= 1) {
#pragma unroll
        for (int s = k >> 1; s > 0; s >>= 1) {
            float ov = __shfl_xor_sync(FULL, v, s);
            int   oj = __shfl_xor_sync(FULL, j, s);
            bool ob = (ov > v) || (ov == v && oj < j);   // other is better
            bool up = ((lane & k) == 0) == ((lane & s) == 0);
            if (up ? ob : !ob) { v = ov; j = oj; }
        }
    }
}

// Drain one sub-batch's event mask into the warp-distributed sorted top-20
// (lane t<20 holds t-th best; lanes>=20 garbage, never read). Candidate
// pos = jbase + 2*s. Pure-float strict comparator: exact jax.lax.top_k
// order (pd desc, j asc) — tie term provably dead (R10). Adopter =
// take && !take[lane-1] (suffix property). Spurious events (admitted by a
// stale threshold but below the true v19) find take=false on lanes 0..19
// and land only in garbage lanes: provable no-ops.
__device__ __forceinline__ void drain(unsigned qm, const float pdc, const int jbase,
                                      float& v, int& idx, const bool lane0)
{
    while (qm) {
        const int s = __ffs(qm) - 1;
        qm &= qm - 1;
        const float pc = __shfl_sync(FULL, pdc, s);
        const int   jc = jbase + (s << 1);

        float vu = __shfl_up_sync(FULL, v,   1);
        int   iu = __shfl_up_sync(FULL, idx, 1);
        bool take  = pc > v;
        bool takeU = pc > vu;
        bool at = take && (lane0 || !takeU);     // unique adopter
        float vn = take ? vu : v;
        int   in = take ? iu : idx;
        v   = at ? pc : vn;
        idx = at ? jc : in;
    }
}

// One 64-candidate block vs one row's list: both ballots use the same
// (possibly stale) tv — stale tv only ADMITS extra no-op events, never
// misses one (tv is monotonically nondecreasing). One merged branch
// region; lo drained fully before hi keeps global j ascending. tv
// refreshed once (not consumed intra-block).
__device__ __forceinline__ void processBlock(const float lo, const float hi, const int B,
                                             float& v, int& idx, float& tv,
                                             const bool lane0)
{
    unsigned qmLo = __ballot_sync(FULL, lo >= tv);
    unsigned qmHi = __ballot_sync(FULL, hi >= tv);
    if (qmLo | qmHi) {
        drain(qmLo, lo, B,     v, idx, lane0);
        drain(qmHi, hi, B + 1, v, idx, lane0);
        tv = __shfl_sync(FULL, v, 19);
    }
}

__device__ __forceinline__ void epilogue(const float* __restrict__ xs,
                                         const float* __restrict__ ys,
                                         const float* __restrict__ zs,
                                         float* __restrict__ out,
                                         const float k0, const float k1, const float k2,
                                         const int b, const int i, const int idx,
                                         const int lane)
{
    const int grow = b * NPTS + i;

    // Output 1: spirals_index (as float); lane t<20 holds the t-th best (pos).
    if (lane < KNN)
        out[(size_t)grow * KNN + lane] = (float)(b * NPTS + invpos(idx));

    int nb[KNN];
#pragma unroll
    for (int kk = 0; kk < KNN; ++kk)
        nb[kk] = __shfl_sync(FULL, idx, kk);       // pos values

    const float q0x = xs[nb[0]], q0y = ys[nb[0]], q0z = zs[nb[0]];
    float w[KNN];
#pragma unroll
    for (int kk = 0; kk < KNN; ++kk) {
        float e0 = xs[nb[kk]] - q0x;
        float e1 = ys[nb[kk]] - q0y;
        float e2 = zs[nb[kk]] - q0z;
        float vv = fmaf(e2, k2, fmaf(e1, k1, __fmul_rn(e0, k0)));
        if (kk == 0 && lane == 0) vv = __fadd_rn(vv, 1.0f);  // one_padding[0][0]
        w[kk] = vv;
    }

    // _top_max over the k axis. Two shared denominators -> one __frcp_rn
    // each + per-element FMUL (<=1ulp drift, inside tolerance; see R11).
    float s1 = 0.0f;
#pragma unroll
    for (int kk = 0; kk < KNN; ++kk) {
        float t = w[kk] > 0.0f ? w[kk] : 0.0f;
        w[kk] = t;
        s1 = __fadd_rn(s1, t);
    }
    const float r1 = __frcp_rn(__fadd_rn(s1, 1e-6f));
    float s2 = 0.0f;
#pragma unroll
    for (int kk = 0; kk < KNN; ++kk) {
        float t = __fmul_rn(w[kk], r1);
        t = __fmul_rn(t, t);
        w[kk] = t;
        s2 = __fadd_rn(s2, t);
    }
    const float r2 = __frcp_rn(__fadd_rn(s2, 1e-6f));

    float* ow = out + IDX_COUNT + (size_t)grow * (KNN * KSW);
#pragma unroll
    for (int kk = 0; kk < KNN; ++kk) {
        float t = __fmul_rn(w[kk], r2);
        ow[kk * KSW + lane] = (t > 0.1f) ? t : 0.0f;
    }
}

__global__ __launch_bounds__(THREADS, 2)
void pai_knn_kernel(const float* __restrict__ x,
                    const float* __restrict__ kern,
                    float* __restrict__ out)
{
    extern __shared__ float smf[];
    float* xs  = smf;               // [NPTS] x, interleaved-64 layout
    float* ys  = smf + NPTS;
    float* zs  = smf + 2 * NPTS;
    float* nws = smf + 3 * NPTS;    // -||p||^2

    const int b    = blockIdx.x >> 7;               // 128 blocks per batch
    const int row0 = (blockIdx.x & 127) * ROWS_PER_BLOCK;
    const float* xb = x + (size_t)b * 3 * NPTS;

    // Stage points (SoA + pairwise interleave).
    // xx = ((x0^2 + x1^2) + x2^2), plain mul/add chain; stored negated.
    for (int t = threadIdx.x; t < NPTS; t += THREADS) {
        float a0 = xb[t];
        float a1 = xb[NPTS + t];
        float a2 = xb[2 * NPTS + t];
        float xx = __fadd_rn(__fadd_rn(__fmul_rn(a0, a0), __fmul_rn(a1, a1)),
                             __fmul_rn(a2, a2));
        const int p = posmap(t);
        xs[p] = a0; ys[p] = a1; zs[p] = a2; nws[p] = -xx;
    }
    __syncthreads();

    const int warp   = threadIdx.x >> 5;
    const int lane   = threadIdx.x & 31;
    const bool lane0 = (lane == 0);
    const int iA     = row0 + warp;          // row A
    const int iB     = iA + 16;              // row B

    const int pA = posmap(iA), pB = posmap(iB);
    const ull PXA = pk2(xs[pA], xs[pA]), PYA = pk2(ys[pA], ys[pA]),
              PZA = pk2(zs[pA], zs[pA]), NXA = pk2(nws[pA], nws[pA]);
    const ull PXB = pk2(xs[pB], xs[pB]), PYB = pk2(ys[pB], ys[pB]),
              PZB = pk2(zs[pB], zs[pB]), NXB = pk2(nws[pB], nws[pB]);
    const ull TWO = pk2(2.0f, 2.0f);

    const int l2 = 2 * lane;

    // Packed pd for one 64-block: lo = pd(j=B+lane), hi = pd(j=B+32+lane).
    // Per-lane chain identical to scalar version -> bit-exact ordering.
#define PDPAIR(B, PX, PY, PZ, NX, LO, HI)                                   \
    {                                                                       \
        ull Xp = *(const ull*)(xs  + (B) + l2);                             \
        ull Yp = *(const ull*)(ys  + (B) + l2);                             \
        ull Zp = *(const ull*)(zs  + (B) + l2);                             \
        ull Wp = *(const ull*)(nws + (B) + l2);                             \
        ull Dp  = fma2(PZ, Zp, fma2(PY, Yp, mul2(PX, Xp)));                 \
        ull PDp = add2(fma2(TWO, Dp, Wp), NX);                              \
        upk2(PDp, LO, HI);                                                  \
    }

    float vA, tvA, vB, tvB;
    int idxA, idxB;

    // ---- Peel block 0 (candidates 0..63): bitonic seed on j=0..31 (lo),
    // then drain the hi half against the fresh threshold.
    {
        float loA, hiA, loB, hiB;
        PDPAIR(0, PXA, PYA, PZA, NXA, loA, hiA);
        PDPAIR(0, PXB, PYB, PZB, NXB, loB, hiB);

        vA = loA; idxA = l2;                  // pos of j=lane
        bitonic32(vA, idxA, lane);
        tvA = __shfl_sync(FULL, vA, 19);

        vB = loB; idxB = l2;
        bitonic32(vB, idxB, lane);
        tvB = __shfl_sync(FULL, vB, 19);

        unsigned qh = __ballot_sync(FULL, hiA >= tvA);
        if (qh) { drain(qh, hiA, 1, vA, idxA, lane0); tvA = __shfl_sync(FULL, vA, 19); }
        qh = __ballot_sync(FULL, hiB >= tvB);
        if (qh) { drain(qh, hiB, 1, vB, idxB, lane0); tvB = __shfl_sync(FULL, vB, 19); }
    }

    // ---- Main scan: 63 remaining 64-blocks; loads shared by both rows;
    // one merged branch region per row per block.
#pragma unroll 2
    for (int blk = 1; blk < NPTS / 64; ++blk) {
        const int B = blk * 64;
        float loA, hiA, loB, hiB;
        PDPAIR(B, PXA, PYA, PZA, NXA, loA, hiA);
        PDPAIR(B, PXB, PYB, PZB, NXB, loB, hiB);

        processBlock(loA, hiA, B, vA, idxA, tvA, lane0);
        processBlock(loB, hiB, B, vB, idxB, tvB, lane0);
    }
#undef PDPAIR

    const float k0 = kern[lane];
    const float k1 = kern[KSW + lane];
    const float k2 = kern[2 * KSW + lane];

    epilogue(xs, ys, zs, out, k0, k1, k2, b, iA, idxA, lane);
    epilogue(xs, ys, zs, out, k0, k1, k2, b, iB, idxB, lane);
}

extern "C" void kernel_launch(void* const* d_in, const int* in_sizes, int n_in,
                              void* d_out, int out_size)
{
    const float* x    = (const float*)d_in[0];
    const float* kern = (const float*)d_in[1];

    (void)in_sizes; (void)n_in; (void)out_size;

    cudaFuncSetAttribute(pai_knn_kernel,
                         cudaFuncAttributeMaxDynamicSharedMemorySize,
                         4 * NPTS * sizeof(float));

    dim3 grid(BATCH * (NPTS / ROWS_PER_BLOCK));   // 1024 blocks
    pai_knn_kernel<<<grid, THREADS, 4 * NPTS * sizeof(float)>>>(x, kern, (float*)d_out);
}

// round 16
// speedup vs baseline: 1.0251x; 1.0251x over previous
#include <cuda_runtime.h>
#include <math_constants.h>

#define BATCH 8
#define NPTS  4096
#define KNN   20
#define KSW   32
#define ROWS_PER_BLOCK 32     // 16 warps x 2 rows
#define THREADS 512
#define FULL 0xffffffffu

#define IDX_COUNT (BATCH * NPTS * KNN)

typedef unsigned long long ull;

// ---- f32x2 packed helpers (sm_103a; per-lane IEEE fp32 RN, bit-exact) ----
__device__ __forceinline__ ull pk2(float lo, float hi)
{ ull r; asm("mov.b64 %0, {%1, %2};" : "=l"(r) : "f"(lo), "f"(hi)); return r; }
__device__ __forceinline__ void upk2(ull p, float& lo, float& hi)
{ asm("mov.b64 {%0, %1}, %2;" : "=f"(lo), "=f"(hi) : "l"(p)); }
__device__ __forceinline__ ull fma2(ull a, ull b, ull c)
{ ull r; asm("fma.rn.f32x2 %0, %1, %2, %3;" : "=l"(r) : "l"(a), "l"(b), "l"(c)); return r; }
__device__ __forceinline__ ull mul2(ull a, ull b)
{ ull r; asm("mul.rn.f32x2 %0, %1, %2;" : "=l"(r) : "l"(a), "l"(b)); return r; }
__device__ __forceinline__ ull add2(ull a, ull b)
{ ull r; asm("add.rn.f32x2 %0, %1, %2;" : "=l"(r) : "l"(a), "l"(b)); return r; }

// SoA position map: within each 64-block, pos = B + 2*(j&31) + ((j>>5)&1).
// A single LDS.64 at B+2*lane yields {j=B+lane (lo), j=B+32+lane (hi)} packed.
__device__ __forceinline__ int posmap(int j)
{ return (j & ~63) + 2 * (j & 31) + ((j >> 5) & 1); }
__device__ __forceinline__ int invpos(int p)
{ return (p & ~63) + ((p >> 1) & 31) + ((p & 1) << 5); }

// Full bitonic sort of 32 (v, p) pairs across the warp, descending by
// (v desc, p asc on ties). Seed elements all have h=0 in one block, so pos
// order == original-j order; 2-field comparator required here.
__device__ __forceinline__ void bitonic32(float& v, int& j, const int lane)
{
#pragma unroll
    for (int k = 2; k <= 32; k <<= 1) {
#pragma unroll
        for (int s = k >> 1; s > 0; s >>= 1) {
            float ov = __shfl_xor_sync(FULL, v, s);
            int   oj = __shfl_xor_sync(FULL, j, s);
            bool ob = (ov > v) || (ov == v && oj < j);   // other is better
            bool up = ((lane & k) == 0) == ((lane & s) == 0);
            if (up ? ob : !ob) { v = ov; j = oj; }
        }
    }
}

// One 32-candidate sub-batch vs the warp-distributed sorted top-20 (lane
// t<20 holds t-th best). Candidate pos = jbase + 2*s (jbase pre-includes the
// h bit). Processing remains in globally ascending original-j order, so the
// pure-float strict comparator reproduces exact jax.lax.top_k order
// (pd desc, j asc) — tie term provably dead (see R10). Adopter =
// take && !take[lane-1] (suffix property). tv refreshed once per
// batch-with-events (not consumed intra-batch).
__device__ __forceinline__ void processBatch(const float pdc, const int jbase,
                                             float& v, int& idx, float& tv,
                                             const bool lane0)
{
    unsigned qm = __ballot_sync(FULL, pdc >= tv);
    if (qm) {
        do {
            const int s = __ffs(qm) - 1;
            qm &= qm - 1;
            const float pc = __shfl_sync(FULL, pdc, s);
            const int   jc = jbase + (s << 1);

            float vu = __shfl_up_sync(FULL, v,   1);
            int   iu = __shfl_up_sync(FULL, idx, 1);
            bool take  = pc > v;
            bool takeU = pc > vu;
            bool at = take && (lane0 || !takeU);     // unique adopter
            float vn = take ? vu : v;
            int   in = take ? iu : idx;
            v   = at ? pc : vn;
            idx = at ? jc : in;
        } while (qm);
        tv = __shfl_sync(FULL, v, 19);
    }
}

__device__ __forceinline__ void epilogue(const float* __restrict__ xs,
                                         const float* __restrict__ ys,
                                         const float* __restrict__ zs,
                                         float* __restrict__ out,
                                         const float k0, const float k1, const float k2,
                                         const int b, const int i, const int idx,
                                         const int lane)
{
    const int grow = b * NPTS + i;

    // Output 1: spirals_index (as float); lane t<20 holds the t-th best (pos).
    if (lane < KNN)
        out[(size_t)grow * KNN + lane] = (float)(b * NPTS + invpos(idx));

    int nb[KNN];
#pragma unroll
    for (int kk = 0; kk < KNN; ++kk)
        nb[kk] = __shfl_sync(FULL, idx, kk);       // pos values

    const float q0x = xs[nb[0]], q0y = ys[nb[0]], q0z = zs[nb[0]];
    float w[KNN];
#pragma unroll
    for (int kk = 0; kk < KNN; ++kk) {
        float e0 = xs[nb[kk]] - q0x;
        float e1 = ys[nb[kk]] - q0y;
        float e2 = zs[nb[kk]] - q0z;
        float vv = fmaf(e2, k2, fmaf(e1, k1, __fmul_rn(e0, k0)));
        if (kk == 0 && lane == 0) vv = __fadd_rn(vv, 1.0f);  // one_padding[0][0]
        w[kk] = vv;
    }

    // _top_max over the k axis. Two shared denominators -> one __frcp_rn
    // each + per-element FMUL (<=1ulp drift, inside tolerance; see R11).
    float s1 = 0.0f;
#pragma unroll
    for (int kk = 0; kk < KNN; ++kk) {
        float t = w[kk] > 0.0f ? w[kk] : 0.0f;
        w[kk] = t;
        s1 = __fadd_rn(s1, t);
    }
    const float r1 = __frcp_rn(__fadd_rn(s1, 1e-6f));
    float s2 = 0.0f;
#pragma unroll
    for (int kk = 0; kk < KNN; ++kk) {
        float t = __fmul_rn(w[kk], r1);
        t = __fmul_rn(t, t);
        w[kk] = t;
        s2 = __fadd_rn(s2, t);
    }
    const float r2 = __frcp_rn(__fadd_rn(s2, 1e-6f));

    float* ow = out + IDX_COUNT + (size_t)grow * (KNN * KSW);
#pragma unroll
    for (int kk = 0; kk < KNN; ++kk) {
        float t = __fmul_rn(w[kk], r2);
        ow[kk * KSW + lane] = (t > 0.1f) ? t : 0.0f;
    }
}

__global__ __launch_bounds__(THREADS, 2)
void pai_knn_kernel(const float* __restrict__ x,
                    const float* __restrict__ kern,
                    float* __restrict__ out)
{
    extern __shared__ float smf[];
    float* xs  = smf;               // [NPTS] x, interleaved-64 layout
    float* ys  = smf + NPTS;
    float* zs  = smf + 2 * NPTS;
    float* nws = smf + 3 * NPTS;    // -||p||^2

    const int b    = blockIdx.x >> 7;               // 128 blocks per batch
    const int row0 = (blockIdx.x & 127) * ROWS_PER_BLOCK;
    const float* xb = x + (size_t)b * 3 * NPTS;

    // Stage points (SoA + pairwise interleave).
    // xx = ((x0^2 + x1^2) + x2^2), plain mul/add chain; stored negated.
    for (int t = threadIdx.x; t < NPTS; t += THREADS) {
        float a0 = xb[t];
        float a1 = xb[NPTS + t];
        float a2 = xb[2 * NPTS + t];
        float xx = __fadd_rn(__fadd_rn(__fmul_rn(a0, a0), __fmul_rn(a1, a1)),
                             __fmul_rn(a2, a2));
        const int p = posmap(t);
        xs[p] = a0; ys[p] = a1; zs[p] = a2; nws[p] = -xx;
    }
    __syncthreads();

    const int warp   = threadIdx.x >> 5;
    const int lane   = threadIdx.x & 31;
    const bool lane0 = (lane == 0);
    const int iA     = row0 + warp;          // row A
    const int iB     = iA + 16;              // row B

    const int pA = posmap(iA), pB = posmap(iB);
    const ull PXA = pk2(xs[pA], xs[pA]), PYA = pk2(ys[pA], ys[pA]),
              PZA = pk2(zs[pA], zs[pA]), NXA = pk2(nws[pA], nws[pA]);
    const ull PXB = pk2(xs[pB], xs[pB]), PYB = pk2(ys[pB], ys[pB]),
              PZB = pk2(zs[pB], zs[pB]), NXB = pk2(nws[pB], nws[pB]);
    const ull TWO = pk2(2.0f, 2.0f);

    const int l2 = 2 * lane;

    // Packed pd for one 64-block: lo = pd(j=B+lane), hi = pd(j=B+32+lane).
    // Per-lane chain identical to scalar version -> bit-exact ordering.
#define PDPAIR(B, PX, PY, PZ, NX, LO, HI)                                   \
    {                                                                       \
        ull Xp = *(const ull*)(xs  + (B) + l2);                             \
        ull Yp = *(const ull*)(ys  + (B) + l2);                             \
        ull Zp = *(const ull*)(zs  + (B) + l2);                             \
        ull Wp = *(const ull*)(nws + (B) + l2);                             \
        ull Dp  = fma2(PZ, Zp, fma2(PY, Yp, mul2(PX, Xp)));                 \
        ull PDp = add2(fma2(TWO, Dp, Wp), NX);                              \
        upk2(PDp, LO, HI);                                                  \
    }

    float vA, tvA, vB, tvB;
    int idxA, idxB;

    // ---- Peel blocks 0 and 1 (candidates 0..127): bitonic seed on j=0..31.
    {
        float loA, hiA, loB, hiB;
        PDPAIR(0, PXA, PYA, PZA, NXA, loA, hiA);
        PDPAIR(0, PXB, PYB, PZB, NXB, loB, hiB);

        vA = loA; idxA = l2;                  // pos of j=lane
        bitonic32(vA, idxA, lane);
        tvA = __shfl_sync(FULL, vA, 19);

        vB = loB; idxB = l2;
        bitonic32(vB, idxB, lane);
        tvB = __shfl_sync(FULL, vB, 19);

        processBatch(hiA, 1, vA, idxA, tvA, lane0);   // j=32..63
        processBatch(hiB, 1, vB, idxB, tvB, lane0);

        PDPAIR(64, PXA, PYA, PZA, NXA, loA, hiA);
        PDPAIR(64, PXB, PYB, PZB, NXB, loB, hiB);
        processBatch(loA, 64, vA, idxA, tvA, lane0);  // j=64..95
        processBatch(loB, 64, vB, idxB, tvB, lane0);
        processBatch(hiA, 65, vA, idxA, tvA, lane0);  // j=96..127
        processBatch(hiB, 65, vB, idxB, tvB, lane0);
    }

    // ---- Main scan: 62 remaining 64-blocks; loads shared by both rows.
#pragma unroll 4
    for (int blk = 2; blk < NPTS / 64; ++blk) {
        const int B = blk * 64;
        float loA, hiA, loB, hiB;
        PDPAIR(B, PXA, PYA, PZA, NXA, loA, hiA);
        PDPAIR(B, PXB, PYB, PZB, NXB, loB, hiB);

        processBatch(loA, B,     vA, idxA, tvA, lane0);
        processBatch(loB, B,     vB, idxB, tvB, lane0);
        processBatch(hiA, B + 1, vA, idxA, tvA, lane0);
        processBatch(hiB, B + 1, vB, idxB, tvB, lane0);
    }
#undef PDPAIR

    const float k0 = kern[lane];
    const float k1 = kern[KSW + lane];
    const float k2 = kern[2 * KSW + lane];

    epilogue(xs, ys, zs, out, k0, k1, k2, b, iA, idxA, lane);
    epilogue(xs, ys, zs, out, k0, k1, k2, b, iB, idxB, lane);
}

extern "C" void kernel_launch(void* const* d_in, const int* in_sizes, int n_in,
                              void* d_out, int out_size)
{
    const float* x    = (const float*)d_in[0];
    const float* kern = (const float*)d_in[1];

    (void)in_sizes; (void)n_in; (void)out_size;

    cudaFuncSetAttribute(pai_knn_kernel,
                         cudaFuncAttributeMaxDynamicSharedMemorySize,
                         4 * NPTS * sizeof(float));

    dim3 grid(BATCH * (NPTS / ROWS_PER_BLOCK));   // 1024 blocks
    pai_knn_kernel<<<grid, THREADS, 4 * NPTS * sizeof(float)>>>(x, kern, (float*)d_out);
}